// round 6
// baseline (speedup 1.0000x reference)
#include <cuda_runtime.h>
#include <math.h>

// Clockwork RNN, hierarchically decomposed.
// B=128, T=512, I=2, H=1024, NM=8, MS=128.
// Round 6: revert to R4 single-stream schedule; chains rebuilt as split-K-4
// (512 threads, 4 threads per output unit) to shorten the per-step critical
// path. GEMM/pout/assemble identical to R4.

#define NB   128
#define NT   512
#define NH   1024
#define NMOD 8
#define MSZ  128

__constant__ int c_TOFF[8] = {0, 513, 770, 899, 964, 997, 1014, 1023};
__constant__ long long c_GOFF[8] = {0, 0, 4210688, 8437760, 11632640,
                                    13795328, 15187968, 16072704};

__device__ float g_traj[16842752];   // 1028 states * 128 b * 128
__device__ float g_G[16646144];      // per-module context GEMM outputs
__device__ float g_pout[1028 * NB * 2];

// packed f32x2 helpers ------------------------------------------------------
__device__ __forceinline__ void fma2(unsigned long long& d,
                                     unsigned long long a,
                                     unsigned long long b) {
    asm("fma.rn.f32x2 %0, %1, %2, %0;" : "+l"(d) : "l"(a), "l"(b));
}
__device__ __forceinline__ unsigned long long add2(unsigned long long a,
                                                   unsigned long long b) {
    unsigned long long d;
    asm("add.rn.f32x2 %0, %1, %2;" : "=l"(d) : "l"(a), "l"(b));
    return d;
}
union U4 { float4 f; unsigned long long u[2]; };
union U2 { unsigned long long u; float2 f; };

__device__ __forceinline__ float fast_tanh(float v) {
    float e = __expf(2.f * v);
    return 1.f - __fdividef(2.f, e + 1.f);
}

// ---------------------------------------------------------------------------
// Sequential diagonal chain for module M, split-K-4.
// 512 threads: rr = tid&127 -> output unit, q = tid>>7 -> K-quarter.
// Each thread holds 32 diag weights (16 packed regs); partials combined in
// smem; q==0 lane does context gathers, tanh, and the state store.
// ---------------------------------------------------------------------------
template <int M>
__global__ __launch_bounds__(512, 1) void chain_kernel(
    const float* __restrict__ x,
    const float* __restrict__ W_ih,
    const float* __restrict__ W_hh,
    const float* __restrict__ enc_w) {
    const int b = blockIdx.x;
    const int tid = threadIdx.x;
    const int rr = tid & 127;
    const int q = tid >> 7;
    const int mbase = M * MSZ;
    __shared__ float h_s[2][MSZ];
    __shared__ float part[3][MSZ];

    // quarter of the diag row: cols [mbase + q*32, mbase + q*32 + 32)
    unsigned long long Wp[16];
#pragma unroll
    for (int c4 = 0; c4 < 8; c4++) {
        U4 w;
        w.f = *(const float4*)(W_hh + (size_t)(mbase + rr) * NH + mbase +
                               q * 32 + c4 * 4);
        Wp[2 * c4 + 0] = w.u[0];
        Wp[2 * c4 + 1] = w.u[1];
    }

    float wih0 = 0.f, wih1 = 0.f;
    const size_t tbase = ((size_t)c_TOFF[M] * NB + b) * MSZ;
    if (q == 0) {
        wih0 = W_ih[(mbase + rr) * 2 + 0];
        wih1 = W_ih[(mbase + rr) * 2 + 1];
        const float x00 = x[(size_t)b * (NT + 1) * 2 + 0];
        const float x01 = x[(size_t)b * (NT + 1) * 2 + 1];
        const float h0v = x00 * enc_w[(mbase + rr) * 2 + 0] +
                          x01 * enc_w[(mbase + rr) * 2 + 1];
        h_s[0][rr] = h0v;
        g_traj[tbase + rr] = h0v;
    }
    __syncthreads();

    const int K = NT >> M;

    float xn0 = 0.f, xn1 = 0.f, gg[8];
    if (q == 0) {
        xn0 = x[((size_t)b * (NT + 1) + 1) * 2 + 0];
        xn1 = x[((size_t)b * (NT + 1) + 1) * 2 + 1];
#pragma unroll
        for (int mp = M + 1; mp < NMOD; mp++)
            gg[mp - M - 1] =
                g_G[c_GOFF[mp] + (size_t)b * (mp * MSZ) + mbase + rr];
    }

    int p = 0;
    for (int k = 0; k < K; k++) {
        // partial dot over my 32 columns
        unsigned long long acc[4] = {0, 0, 0, 0};
        const float4* h4 = (const float4*)&h_s[p][q * 32];
#pragma unroll
        for (int c4 = 0; c4 < 8; c4++) {
            U4 hv;
            hv.f = h4[c4];
            fma2(acc[(2 * c4) & 3], Wp[2 * c4], hv.u[0]);
            fma2(acc[(2 * c4 + 1) & 3], Wp[2 * c4 + 1], hv.u[1]);
        }
        acc[0] = add2(acc[0], acc[1]);
        acc[2] = add2(acc[2], acc[3]);
        acc[0] = add2(acc[0], acc[2]);
        U2 a;
        a.u = acc[0];
        const float partial = a.f.x + a.f.y;
        if (q) part[q - 1][rr] = partial;

        // q==0: fold context + prefetch next step's gathers
        float gsum = 0.f, xt0 = 0.f, xt1 = 0.f, gt[8];
        if (q == 0) {
            gsum = xn0 * wih0 + xn1 * wih1;
#pragma unroll
            for (int mp = M + 1; mp < NMOD; mp++) gsum += gg[mp - M - 1];
            if (k + 1 < K) {
                const int t2 = (k + 1) << M;
                xt0 = x[((size_t)b * (NT + 1) + (t2 + 1)) * 2 + 0];
                xt1 = x[((size_t)b * (NT + 1) + (t2 + 1)) * 2 + 1];
#pragma unroll
                for (int mp = M + 1; mp < NMOD; mp++) {
                    const int s = ((t2 - 1) >> mp) + 1;
                    gt[mp - M - 1] = g_G[c_GOFF[mp] +
                                         (size_t)(s * NB + b) * (mp * MSZ) +
                                         mbase + rr];
                }
            }
        }
        __syncthreads();

        if (q == 0) {
            const float tot = partial + part[0][rr] + part[1][rr] +
                              part[2][rr] + gsum;
            const float hn = fast_tanh(tot);
            h_s[p ^ 1][rr] = hn;
            g_traj[tbase + (size_t)(k + 1) * (NB * MSZ) + rr] = hn;
            xn0 = xt0; xn1 = xt1;
#pragma unroll
            for (int mp = M + 1; mp < NMOD; mp++)
                gg[mp - M - 1] = gt[mp - M - 1];
        }
        __syncthreads();
        p ^= 1;
    }
}

// ---------------------------------------------------------------------------
// G_{mp} = Traj_{mp} (S_mp*128 x 128) @ W_hh[0:mp*128, mp-block]^T
// 64x64 tile, 256 threads, 4x4 packed-f32x2 micro-tile, 2 CTAs/SM. (as R4)
// ---------------------------------------------------------------------------
__global__ __launch_bounds__(256, 2) void g_kernel(const float* __restrict__ W_hh,
                                                   int mp) {
    __shared__ float As[2][64][20];
    __shared__ float Bs[2][64][20];
    const int N = mp * MSZ;
    const float* A = g_traj + (size_t)c_TOFF[mp] * (NB * MSZ);
    float* C = g_G + c_GOFF[mp];
    const int row0 = blockIdx.x * 64;
    const int n0 = blockIdx.y * 64;
    const int tid = threadIdx.x;
    const int tx = tid & 15;
    const int ty = tid >> 4;

    const int lrow = tid >> 2, lc4 = tid & 3;

    const float* Ap = A + (size_t)(row0 + lrow) * MSZ + lc4 * 4;
    const float* Bp = W_hh + (size_t)(n0 + lrow) * NH + mp * MSZ + lc4 * 4;

    float4 pa = *(const float4*)Ap;
    float4 pb = *(const float4*)Bp;
    *(float4*)&As[0][lrow][lc4 * 4] = pa;
    *(float4*)&Bs[0][lrow][lc4 * 4] = pb;
    __syncthreads();

    unsigned long long acc[4][4];
#pragma unroll
    for (int i = 0; i < 4; i++)
#pragma unroll
        for (int j = 0; j < 4; j++) acc[i][j] = 0ull;

#pragma unroll
    for (int c = 0; c < 8; c++) {
        const int buf = c & 1;
        if (c < 7) {
            pa = *(const float4*)(Ap + (c + 1) * 16);
            pb = *(const float4*)(Bp + (c + 1) * 16);
        }
#pragma unroll
        for (int k4 = 0; k4 < 4; k4++) {
            U4 af[4], bf[4];
#pragma unroll
            for (int i = 0; i < 4; i++)
                af[i].f = *(const float4*)&As[buf][ty * 4 + i][k4 * 4];
#pragma unroll
            for (int j = 0; j < 4; j++)
                bf[j].f = *(const float4*)&Bs[buf][tx + j * 16][k4 * 4];
#pragma unroll
            for (int i = 0; i < 4; i++)
#pragma unroll
                for (int j = 0; j < 4; j++) {
                    fma2(acc[i][j], af[i].u[0], bf[j].u[0]);
                    fma2(acc[i][j], af[i].u[1], bf[j].u[1]);
                }
        }
        if (c < 7) {
            const int nb = buf ^ 1;
            *(float4*)&As[nb][lrow][lc4 * 4] = pa;
            *(float4*)&Bs[nb][lrow][lc4 * 4] = pb;
            __syncthreads();
        }
    }

#pragma unroll
    for (int i = 0; i < 4; i++)
#pragma unroll
        for (int j = 0; j < 4; j++) {
            U2 a;
            a.u = acc[i][j];
            C[(size_t)(row0 + ty * 4 + i) * N + n0 + tx + j * 16] =
                a.f.x + a.f.y;
        }
}

// ---------------------------------------------------------------------------
// fc partials: one CTA per stored state; 8 warps sweep the 128 batch rows.
// ---------------------------------------------------------------------------
__global__ __launch_bounds__(256) void pout_kernel(
    const float* __restrict__ fc_w) {
    const int gs = blockIdx.x;
    const int warp = threadIdx.x >> 5;
    const int lane = threadIdx.x & 31;
    int m = 0;
#pragma unroll
    for (int j = 1; j < 8; j++)
        if (gs >= c_TOFF[j]) m = j;
    const int col = m * MSZ + lane * 4;
    const float4 w0 = *(const float4*)(fc_w + col);
    const float4 w1 = *(const float4*)(fc_w + NH + col);
    const float* base = g_traj + (size_t)gs * (NB * MSZ);

    for (int b = warp; b < NB; b += 8) {
        const float4 v = *(const float4*)(base + (size_t)b * MSZ + lane * 4);
        float a0 = v.x * w0.x + v.y * w0.y + v.z * w0.z + v.w * w0.w;
        float a1 = v.x * w1.x + v.y * w1.y + v.z * w1.z + v.w * w1.w;
#pragma unroll
        for (int off = 16; off > 0; off >>= 1) {
            a0 += __shfl_xor_sync(0xffffffffu, a0, off);
            a1 += __shfl_xor_sync(0xffffffffu, a1, off);
        }
        if (lane == 0) {
            g_pout[((size_t)gs * NB + b) * 2 + 0] = a0;
            g_pout[((size_t)gs * NB + b) * 2 + 1] = a1;
        }
    }
}

// ---------------------------------------------------------------------------
// out[b,t,i] = fc_b[i] + sum_m pout[state_of(m,t), b, i]
// ---------------------------------------------------------------------------
__global__ void assemble_kernel(const float* __restrict__ fc_b,
                                float* __restrict__ out) {
    const int idx = blockIdx.x * blockDim.x + threadIdx.x;  // b*512 + t
    const int b = idx >> 9;
    const int t = idx & 511;
    float o0 = fc_b[0];
    float o1 = fc_b[1];
#pragma unroll
    for (int m = 0; m < NMOD; m++) {
        const int gs = c_TOFF[m] + (t >> m) + 1;
        o0 += g_pout[((size_t)gs * NB + b) * 2 + 0];
        o1 += g_pout[((size_t)gs * NB + b) * 2 + 1];
    }
    out[(size_t)idx * 2 + 0] = o0;
    out[(size_t)idx * 2 + 1] = o1;
}

// ---------------------------------------------------------------------------
extern "C" void kernel_launch(void* const* d_in, const int* in_sizes, int n_in,
                              void* d_out, int out_size) {
    const float* x     = (const float*)d_in[0];
    const float* W_ih  = (const float*)d_in[1];
    const float* W_hh  = (const float*)d_in[2];
    const float* fc_w  = (const float*)d_in[3];
    const float* fc_b  = (const float*)d_in[4];
    const float* enc_w = (const float*)d_in[5];
    float* out = (float*)d_out;

    // S_mp = {_,257,129,65,33,17,9,5}; grid = (2*S_mp, 2*mp) for 64x64 tiles
    chain_kernel<7><<<NB, 512>>>(x, W_ih, W_hh, enc_w);
    g_kernel<<<dim3(10, 14), 256>>>(W_hh, 7);
    chain_kernel<6><<<NB, 512>>>(x, W_ih, W_hh, enc_w);
    g_kernel<<<dim3(18, 12), 256>>>(W_hh, 6);
    chain_kernel<5><<<NB, 512>>>(x, W_ih, W_hh, enc_w);
    g_kernel<<<dim3(34, 10), 256>>>(W_hh, 5);
    chain_kernel<4><<<NB, 512>>>(x, W_ih, W_hh, enc_w);
    g_kernel<<<dim3(66, 8), 256>>>(W_hh, 4);
    chain_kernel<3><<<NB, 512>>>(x, W_ih, W_hh, enc_w);
    g_kernel<<<dim3(130, 6), 256>>>(W_hh, 3);
    chain_kernel<2><<<NB, 512>>>(x, W_ih, W_hh, enc_w);
    g_kernel<<<dim3(258, 4), 256>>>(W_hh, 2);
    chain_kernel<1><<<NB, 512>>>(x, W_ih, W_hh, enc_w);
    g_kernel<<<dim3(514, 2), 256>>>(W_hh, 1);
    chain_kernel<0><<<NB, 512>>>(x, W_ih, W_hh, enc_w);

    pout_kernel<<<1028, 256>>>(fc_w);
    assemble_kernel<<<(NB * NT) / 256, 256>>>(fc_b, out);
}

// round 7
// speedup vs baseline: 1.1051x; 1.1051x over previous
#include <cuda_runtime.h>
#include <math.h>

// Clockwork RNN, hierarchically decomposed.
// B=128, T=512, I=2, H=1024, NM=8, MS=128.
// Round 7: R4 chains (128 thr, one barrier/step) + deadline-ordered two-stream
// schedule. Critical path = chains + urgent (next-chain) G blocks only; all
// other G blocks + fc partials run on stream1, ordered by consumer deadline.

#define NB   128
#define NT   512
#define NH   1024
#define NMOD 8
#define MSZ  128

__constant__ int c_TOFF[8] = {0, 513, 770, 899, 964, 997, 1014, 1023};
__constant__ long long c_GOFF[8] = {0, 0, 4210688, 8437760, 11632640,
                                    13795328, 15187968, 16072704};

__device__ float g_traj[16842752];   // 1028 states * 128 b * 128
__device__ float g_G[16646144];      // per-module context GEMM outputs
__device__ float g_pout[1028 * NB * 2];

// packed f32x2 helpers ------------------------------------------------------
__device__ __forceinline__ void fma2(unsigned long long& d,
                                     unsigned long long a,
                                     unsigned long long b) {
    asm("fma.rn.f32x2 %0, %1, %2, %0;" : "+l"(d) : "l"(a), "l"(b));
}
__device__ __forceinline__ unsigned long long add2(unsigned long long a,
                                                   unsigned long long b) {
    unsigned long long d;
    asm("add.rn.f32x2 %0, %1, %2;" : "=l"(d) : "l"(a), "l"(b));
    return d;
}
union U4 { float4 f; unsigned long long u[2]; };
union U2 { unsigned long long u; float2 f; };

__device__ __forceinline__ float fast_tanh(float v) {
    float e = __expf(2.f * v);
    return 1.f - __fdividef(2.f, e + 1.f);
}

// ---------------------------------------------------------------------------
// Sequential diagonal chain for module M (R4 version: 128 thr, 1 barrier).
// ---------------------------------------------------------------------------
template <int M>
__global__ __launch_bounds__(MSZ, 1) void chain_kernel(
    const float* __restrict__ x,
    const float* __restrict__ W_ih,
    const float* __restrict__ W_hh,
    const float* __restrict__ enc_w) {
    const int b = blockIdx.x;
    const int r = threadIdx.x;
    const int mbase = M * MSZ;
    __shared__ float h_s[2][MSZ];

    unsigned long long Wp[MSZ / 2];
#pragma unroll
    for (int c4 = 0; c4 < MSZ / 4; c4++) {
        U4 w;
        w.f = *(const float4*)(W_hh + (size_t)(mbase + r) * NH + mbase +
                               c4 * 4);
        Wp[2 * c4 + 0] = w.u[0];
        Wp[2 * c4 + 1] = w.u[1];
    }
    const float wih0 = W_ih[(mbase + r) * 2 + 0];
    const float wih1 = W_ih[(mbase + r) * 2 + 1];

    const float x00 = x[(size_t)b * (NT + 1) * 2 + 0];
    const float x01 = x[(size_t)b * (NT + 1) * 2 + 1];
    const float h0v = x00 * enc_w[(mbase + r) * 2 + 0] +
                      x01 * enc_w[(mbase + r) * 2 + 1];
    const size_t tbase = ((size_t)c_TOFF[M] * NB + b) * MSZ;
    h_s[0][r] = h0v;
    g_traj[tbase + r] = h0v;
    __syncthreads();

    const int K = NT >> M;

    float xn0 = x[((size_t)b * (NT + 1) + 1) * 2 + 0];
    float xn1 = x[((size_t)b * (NT + 1) + 1) * 2 + 1];
    float gg[8];
#pragma unroll
    for (int mp = M + 1; mp < NMOD; mp++)
        gg[mp - M - 1] =
            g_G[c_GOFF[mp] + (size_t)b * (mp * MSZ) + mbase + r];

    int p = 0;
    for (int k = 0; k < K; k++) {
        float gsum = xn0 * wih0 + xn1 * wih1;
#pragma unroll
        for (int mp = M + 1; mp < NMOD; mp++) gsum += gg[mp - M - 1];

        float xt0 = 0.f, xt1 = 0.f, gt[8];
        if (k + 1 < K) {
            const int t2 = (k + 1) << M;
            xt0 = x[((size_t)b * (NT + 1) + (t2 + 1)) * 2 + 0];
            xt1 = x[((size_t)b * (NT + 1) + (t2 + 1)) * 2 + 1];
#pragma unroll
            for (int mp = M + 1; mp < NMOD; mp++) {
                const int s = ((t2 - 1) >> mp) + 1;
                gt[mp - M - 1] = g_G[c_GOFF[mp] +
                                     (size_t)(s * NB + b) * (mp * MSZ) +
                                     mbase + r];
            }
        }

        unsigned long long acc[8] = {0, 0, 0, 0, 0, 0, 0, 0};
        const float4* h4 = (const float4*)h_s[p];
#pragma unroll
        for (int c4 = 0; c4 < MSZ / 4; c4++) {
            U4 hv;
            hv.f = h4[c4];
            fma2(acc[(2 * c4) & 7], Wp[2 * c4], hv.u[0]);
            fma2(acc[(2 * c4 + 1) & 7], Wp[2 * c4 + 1], hv.u[1]);
        }
        acc[0] = add2(acc[0], acc[1]);
        acc[2] = add2(acc[2], acc[3]);
        acc[4] = add2(acc[4], acc[5]);
        acc[6] = add2(acc[6], acc[7]);
        acc[0] = add2(acc[0], acc[2]);
        acc[4] = add2(acc[4], acc[6]);
        acc[0] = add2(acc[0], acc[4]);
        U2 a;
        a.u = acc[0];
        const float hn = fast_tanh(a.f.x + a.f.y + gsum);

        h_s[p ^ 1][r] = hn;
        g_traj[tbase + (size_t)(k + 1) * (NB * MSZ) + r] = hn;
        __syncthreads();
        p ^= 1;

        xn0 = xt0; xn1 = xt1;
#pragma unroll
        for (int mp = M + 1; mp < NMOD; mp++) gg[mp - M - 1] = gt[mp - M - 1];
    }
}

// ---------------------------------------------------------------------------
// One target-block piece of G_{mp} (validated in R5):
//   C[:, Mtgt-block] = Traj_{mp} @ W_hh[Mtgt-block rows, mp-cols]^T
// 64x64 tile, 256 threads, 4x4 packed-f32x2 micro-tile, 2 CTAs/SM.
// ---------------------------------------------------------------------------
__global__ __launch_bounds__(256, 2) void g_piece(const float* __restrict__ W_hh,
                                                  int mp, int Mtgt) {
    __shared__ float As[2][64][20];
    __shared__ float Bs[2][64][20];
    const int N = mp * MSZ;
    const float* A = g_traj + (size_t)c_TOFF[mp] * (NB * MSZ);
    float* C = g_G + c_GOFF[mp] + Mtgt * MSZ;
    const int row0 = blockIdx.x * 64;
    const int n0 = blockIdx.y * 64;
    const int tid = threadIdx.x;
    const int tx = tid & 15;
    const int ty = tid >> 4;

    const int lrow = tid >> 2, lc4 = tid & 3;

    const float* Ap = A + (size_t)(row0 + lrow) * MSZ + lc4 * 4;
    const float* Bp = W_hh + (size_t)(Mtgt * MSZ + n0 + lrow) * NH + mp * MSZ +
                      lc4 * 4;

    float4 pa = *(const float4*)Ap;
    float4 pb = *(const float4*)Bp;
    *(float4*)&As[0][lrow][lc4 * 4] = pa;
    *(float4*)&Bs[0][lrow][lc4 * 4] = pb;
    __syncthreads();

    unsigned long long acc[4][4];
#pragma unroll
    for (int i = 0; i < 4; i++)
#pragma unroll
        for (int j = 0; j < 4; j++) acc[i][j] = 0ull;

#pragma unroll
    for (int c = 0; c < 8; c++) {
        const int buf = c & 1;
        if (c < 7) {
            pa = *(const float4*)(Ap + (c + 1) * 16);
            pb = *(const float4*)(Bp + (c + 1) * 16);
        }
#pragma unroll
        for (int k4 = 0; k4 < 4; k4++) {
            U4 af[4], bf[4];
#pragma unroll
            for (int i = 0; i < 4; i++)
                af[i].f = *(const float4*)&As[buf][ty * 4 + i][k4 * 4];
#pragma unroll
            for (int j = 0; j < 4; j++)
                bf[j].f = *(const float4*)&Bs[buf][tx + j * 16][k4 * 4];
#pragma unroll
            for (int i = 0; i < 4; i++)
#pragma unroll
                for (int j = 0; j < 4; j++) {
                    fma2(acc[i][j], af[i].u[0], bf[j].u[0]);
                    fma2(acc[i][j], af[i].u[1], bf[j].u[1]);
                }
        }
        if (c < 7) {
            const int nb = buf ^ 1;
            *(float4*)&As[nb][lrow][lc4 * 4] = pa;
            *(float4*)&Bs[nb][lrow][lc4 * 4] = pb;
            __syncthreads();
        }
    }

#pragma unroll
    for (int i = 0; i < 4; i++)
#pragma unroll
        for (int j = 0; j < 4; j++) {
            U2 a;
            a.u = acc[i][j];
            C[(size_t)(row0 + ty * 4 + i) * N + n0 + tx + j * 16] =
                a.f.x + a.f.y;
        }
}

// ---------------------------------------------------------------------------
// fc partials for one module's state range; one CTA per state (R5 version).
// ---------------------------------------------------------------------------
__global__ __launch_bounds__(256) void pout_kernel(
    const float* __restrict__ fc_w, int gs0, int m) {
    const int gs = gs0 + blockIdx.x;
    const int warp = threadIdx.x >> 5;
    const int lane = threadIdx.x & 31;
    const int col = m * MSZ + lane * 4;
    const float4 w0 = *(const float4*)(fc_w + col);
    const float4 w1 = *(const float4*)(fc_w + NH + col);
    const float* base = g_traj + (size_t)gs * (NB * MSZ);

    for (int b = warp; b < NB; b += 8) {
        const float4 v = *(const float4*)(base + (size_t)b * MSZ + lane * 4);
        float a0 = v.x * w0.x + v.y * w0.y + v.z * w0.z + v.w * w0.w;
        float a1 = v.x * w1.x + v.y * w1.y + v.z * w1.z + v.w * w1.w;
#pragma unroll
        for (int off = 16; off > 0; off >>= 1) {
            a0 += __shfl_xor_sync(0xffffffffu, a0, off);
            a1 += __shfl_xor_sync(0xffffffffu, a1, off);
        }
        if (lane == 0) {
            g_pout[((size_t)gs * NB + b) * 2 + 0] = a0;
            g_pout[((size_t)gs * NB + b) * 2 + 1] = a1;
        }
    }
}

// ---------------------------------------------------------------------------
// out[b,t,i] = fc_b[i] + sum_m pout[state_of(m,t), b, i]
// ---------------------------------------------------------------------------
__global__ void assemble_kernel(const float* __restrict__ fc_b,
                                float* __restrict__ out) {
    const int idx = blockIdx.x * blockDim.x + threadIdx.x;  // b*512 + t
    const int b = idx >> 9;
    const int t = idx & 511;
    float o0 = fc_b[0];
    float o1 = fc_b[1];
#pragma unroll
    for (int m = 0; m < NMOD; m++) {
        const int gs = c_TOFF[m] + (t >> m) + 1;
        o0 += g_pout[((size_t)gs * NB + b) * 2 + 0];
        o1 += g_pout[((size_t)gs * NB + b) * 2 + 1];
    }
    out[(size_t)idx * 2 + 0] = o0;
    out[(size_t)idx * 2 + 1] = o1;
}

// ---------------------------------------------------------------------------
// Deadline-ordered two-stream schedule.
// stream0: chain7, U7, chain6, U6, [t5] chain5, U5, [t4] chain4, ...,
//          U1, [t0] chain0, pout0, [join] assemble.
// stream1: deferred G pieces ordered by TARGET (descending deadline):
//   all pieces for target tau are enqueued before any piece for tau-1,
//   with tEv[tau] recorded after the last one. Pouts at the tail.
// ---------------------------------------------------------------------------
static const int h_TOFF[8] = {0, 513, 770, 899, 964, 997, 1014, 1023};
static const int h_S[8] = {513, 257, 129, 65, 33, 17, 9, 5};

extern "C" void kernel_launch(void* const* d_in, const int* in_sizes, int n_in,
                              void* d_out, int out_size) {
    const float* x     = (const float*)d_in[0];
    const float* W_ih  = (const float*)d_in[1];
    const float* W_hh  = (const float*)d_in[2];
    const float* fc_w  = (const float*)d_in[3];
    const float* fc_b  = (const float*)d_in[4];
    const float* enc_w = (const float*)d_in[5];
    float* out = (float*)d_out;

    static cudaStream_t s1 = nullptr;
    static cudaEvent_t evFork, evJoin, cEv[8], tEv[8];
    if (!s1) {
        cudaStreamCreateWithFlags(&s1, cudaStreamNonBlocking);
        cudaEventCreateWithFlags(&evFork, cudaEventDisableTiming);
        cudaEventCreateWithFlags(&evJoin, cudaEventDisableTiming);
        for (int i = 0; i < 8; i++) {
            cudaEventCreateWithFlags(&cEv[i], cudaEventDisableTiming);
            cudaEventCreateWithFlags(&tEv[i], cudaEventDisableTiming);
        }
    }
    cudaStream_t s0 = 0;

    cudaEventRecord(evFork, s0);
    cudaStreamWaitEvent(s1, evFork, 0);

    #define RUN_CHAIN(M) chain_kernel<M><<<NB, MSZ, 0, s0>>>(x, W_ih, W_hh, enc_w)
    #define URGENT(MP)   g_piece<<<dim3(2 * h_S[MP], 2), 256, 0, s0>>>(W_hh, MP, (MP) - 1)
    #define DEFER(MP, MT) g_piece<<<dim3(2 * h_S[MP], 2), 256, 0, s1>>>(W_hh, MP, MT)
    #define POUT1(M, SS) pout_kernel<<<h_S[M], 256, 0, SS>>>(fc_w, h_TOFF[M], M)

    // ---- stream0 critical path + stream1 deadline-ordered deferred work ----
    RUN_CHAIN(7);  cudaEventRecord(cEv[7], s0);
    URGENT(7);

    cudaStreamWaitEvent(s1, cEv[7], 0);
    DEFER(7, 5);  cudaEventRecord(tEv[5], s1);          // target 5 complete

    RUN_CHAIN(6);  cudaEventRecord(cEv[6], s0);
    URGENT(6);

    DEFER(7, 4);
    cudaStreamWaitEvent(s1, cEv[6], 0);
    DEFER(6, 4);  cudaEventRecord(tEv[4], s1);          // target 4 complete

    cudaStreamWaitEvent(s0, tEv[5], 0);
    RUN_CHAIN(5);  cudaEventRecord(cEv[5], s0);
    URGENT(5);

    DEFER(7, 3); DEFER(6, 3);
    cudaStreamWaitEvent(s1, cEv[5], 0);
    DEFER(5, 3);  cudaEventRecord(tEv[3], s1);          // target 3 complete

    cudaStreamWaitEvent(s0, tEv[4], 0);
    RUN_CHAIN(4);  cudaEventRecord(cEv[4], s0);
    URGENT(4);

    DEFER(7, 2); DEFER(6, 2); DEFER(5, 2);
    cudaStreamWaitEvent(s1, cEv[4], 0);
    DEFER(4, 2);  cudaEventRecord(tEv[2], s1);          // target 2 complete

    cudaStreamWaitEvent(s0, tEv[3], 0);
    RUN_CHAIN(3);  cudaEventRecord(cEv[3], s0);
    URGENT(3);

    DEFER(7, 1); DEFER(6, 1); DEFER(5, 1); DEFER(4, 1);
    cudaStreamWaitEvent(s1, cEv[3], 0);
    DEFER(3, 1);  cudaEventRecord(tEv[1], s1);          // target 1 complete

    cudaStreamWaitEvent(s0, tEv[2], 0);
    RUN_CHAIN(2);  cudaEventRecord(cEv[2], s0);
    URGENT(2);

    DEFER(7, 0); DEFER(6, 0); DEFER(5, 0); DEFER(4, 0); DEFER(3, 0);
    cudaStreamWaitEvent(s1, cEv[2], 0);
    DEFER(2, 0);  cudaEventRecord(tEv[0], s1);          // target 0 complete

    cudaStreamWaitEvent(s0, tEv[1], 0);
    RUN_CHAIN(1);  cudaEventRecord(cEv[1], s0);
    URGENT(1);

    // deferred pouts (all sources with chains already waited on in s1)
    POUT1(7, s1); POUT1(6, s1); POUT1(5, s1); POUT1(4, s1);
    POUT1(3, s1); POUT1(2, s1);
    cudaStreamWaitEvent(s1, cEv[1], 0);
    POUT1(1, s1);
    cudaEventRecord(evJoin, s1);

    cudaStreamWaitEvent(s0, tEv[0], 0);
    RUN_CHAIN(0);
    POUT1(0, s0);

    cudaStreamWaitEvent(s0, evJoin, 0);
    assemble_kernel<<<(NB * NT) / 256, 256, 0, s0>>>(fc_b, out);

    #undef RUN_CHAIN
    #undef URGENT
    #undef DEFER
    #undef POUT1
}

// round 8
// speedup vs baseline: 1.2314x; 1.1142x over previous
#include <cuda_runtime.h>
#include <math.h>

// Clockwork RNN, hierarchically decomposed.
// B=128, T=512, I=2, H=1024, NM=8, MS=128.
// Round 8: back to R4 serial schedule. g_kernel gets a 3-stage cp.async
// pipeline (no staging regs, loads overlap compute). chain_kernel stages its
// weight block through smem with coalesced loads (2 passes of 64 rows).

#define NB   128
#define NT   512
#define NH   1024
#define NMOD 8
#define MSZ  128

__constant__ int c_TOFF[8] = {0, 513, 770, 899, 964, 997, 1014, 1023};
__constant__ long long c_GOFF[8] = {0, 0, 4210688, 8437760, 11632640,
                                    13795328, 15187968, 16072704};

__device__ float g_traj[16842752];   // 1028 states * 128 b * 128
__device__ float g_G[16646144];      // per-module context GEMM outputs
__device__ float g_pout[1028 * NB * 2];

// packed f32x2 helpers ------------------------------------------------------
__device__ __forceinline__ void fma2(unsigned long long& d,
                                     unsigned long long a,
                                     unsigned long long b) {
    asm("fma.rn.f32x2 %0, %1, %2, %0;" : "+l"(d) : "l"(a), "l"(b));
}
__device__ __forceinline__ unsigned long long add2(unsigned long long a,
                                                   unsigned long long b) {
    unsigned long long d;
    asm("add.rn.f32x2 %0, %1, %2;" : "=l"(d) : "l"(a), "l"(b));
    return d;
}
union U4 { float4 f; unsigned long long u[2]; };
union U2 { unsigned long long u; float2 f; };

__device__ __forceinline__ float fast_tanh(float v) {
    float e = __expf(2.f * v);
    return 1.f - __fdividef(2.f, e + 1.f);
}

__device__ __forceinline__ void cp16(unsigned int dst, const void* src) {
    asm volatile("cp.async.ca.shared.global [%0], [%1], 16;"
                 :: "r"(dst), "l"(src));
}
__device__ __forceinline__ void cp_commit() {
    asm volatile("cp.async.commit_group;");
}
__device__ __forceinline__ void cp_wait1() {
    asm volatile("cp.async.wait_group 1;" ::: "memory");
}
__device__ __forceinline__ void cp_wait0() {
    asm volatile("cp.async.wait_group 0;" ::: "memory");
}

// ---------------------------------------------------------------------------
// Sequential diagonal chain for module M (128 thr, 1 barrier/step).
// Weight block staged through smem with coalesced loads (2 passes).
// ---------------------------------------------------------------------------
template <int M>
__global__ __launch_bounds__(MSZ, 1) void chain_kernel(
    const float* __restrict__ x,
    const float* __restrict__ W_ih,
    const float* __restrict__ W_hh,
    const float* __restrict__ enc_w) {
    const int b = blockIdx.x;
    const int r = threadIdx.x;
    const int mbase = M * MSZ;
    __shared__ float h_s[2][MSZ];
    __shared__ float Wst[64][132];   // 64 rows staged per pass, padded

    unsigned long long Wp[MSZ / 2];
#pragma unroll
    for (int pass = 0; pass < 2; pass++) {
        // coalesced cooperative load of rows [pass*64, pass*64+64)
#pragma unroll
        for (int i = 0; i < 16; i++) {
            const int idx = i * 128 + r;        // 0..2047 float4 slots
            const int row = idx >> 5;           // 0..63
            const int c4 = idx & 31;            // 0..31
            *(float4*)&Wst[row][c4 * 4] =
                *(const float4*)(W_hh +
                                 (size_t)(mbase + pass * 64 + row) * NH +
                                 mbase + c4 * 4);
        }
        __syncthreads();
        if ((r >> 6) == pass) {
            const int rr = r & 63;
#pragma unroll
            for (int c4 = 0; c4 < 32; c4++) {
                U4 w;
                w.f = *(const float4*)&Wst[rr][c4 * 4];
                Wp[2 * c4 + 0] = w.u[0];
                Wp[2 * c4 + 1] = w.u[1];
            }
        }
        __syncthreads();
    }

    const float wih0 = W_ih[(mbase + r) * 2 + 0];
    const float wih1 = W_ih[(mbase + r) * 2 + 1];

    const float x00 = x[(size_t)b * (NT + 1) * 2 + 0];
    const float x01 = x[(size_t)b * (NT + 1) * 2 + 1];
    const float h0v = x00 * enc_w[(mbase + r) * 2 + 0] +
                      x01 * enc_w[(mbase + r) * 2 + 1];
    const size_t tbase = ((size_t)c_TOFF[M] * NB + b) * MSZ;
    h_s[0][r] = h0v;
    g_traj[tbase + r] = h0v;
    __syncthreads();

    const int K = NT >> M;

    float xn0 = x[((size_t)b * (NT + 1) + 1) * 2 + 0];
    float xn1 = x[((size_t)b * (NT + 1) + 1) * 2 + 1];
    float gg[8];
#pragma unroll
    for (int mp = M + 1; mp < NMOD; mp++)
        gg[mp - M - 1] =
            g_G[c_GOFF[mp] + (size_t)b * (mp * MSZ) + mbase + r];

    int p = 0;
    for (int k = 0; k < K; k++) {
        float gsum = xn0 * wih0 + xn1 * wih1;
#pragma unroll
        for (int mp = M + 1; mp < NMOD; mp++) gsum += gg[mp - M - 1];

        float xt0 = 0.f, xt1 = 0.f, gt[8];
        if (k + 1 < K) {
            const int t2 = (k + 1) << M;
            xt0 = x[((size_t)b * (NT + 1) + (t2 + 1)) * 2 + 0];
            xt1 = x[((size_t)b * (NT + 1) + (t2 + 1)) * 2 + 1];
#pragma unroll
            for (int mp = M + 1; mp < NMOD; mp++) {
                const int s = ((t2 - 1) >> mp) + 1;
                gt[mp - M - 1] = g_G[c_GOFF[mp] +
                                     (size_t)(s * NB + b) * (mp * MSZ) +
                                     mbase + r];
            }
        }

        unsigned long long acc[8] = {0, 0, 0, 0, 0, 0, 0, 0};
        const float4* h4 = (const float4*)h_s[p];
#pragma unroll
        for (int c4 = 0; c4 < MSZ / 4; c4++) {
            U4 hv;
            hv.f = h4[c4];
            fma2(acc[(2 * c4) & 7], Wp[2 * c4], hv.u[0]);
            fma2(acc[(2 * c4 + 1) & 7], Wp[2 * c4 + 1], hv.u[1]);
        }
        acc[0] = add2(acc[0], acc[1]);
        acc[2] = add2(acc[2], acc[3]);
        acc[4] = add2(acc[4], acc[5]);
        acc[6] = add2(acc[6], acc[7]);
        acc[0] = add2(acc[0], acc[2]);
        acc[4] = add2(acc[4], acc[6]);
        acc[0] = add2(acc[0], acc[4]);
        U2 a;
        a.u = acc[0];
        const float hn = fast_tanh(a.f.x + a.f.y + gsum);

        h_s[p ^ 1][r] = hn;
        g_traj[tbase + (size_t)(k + 1) * (NB * MSZ) + r] = hn;
        __syncthreads();
        p ^= 1;

        xn0 = xt0; xn1 = xt1;
#pragma unroll
        for (int mp = M + 1; mp < NMOD; mp++) gg[mp - M - 1] = gt[mp - M - 1];
    }
}

// ---------------------------------------------------------------------------
// G_{mp} = Traj_{mp} (S_mp*128 x 128) @ W_hh[0:mp*128, mp-block]^T
// 64x64 tile, 256 threads, 4x4 packed-f32x2 micro-tile, 2 CTAs/SM.
// 3-stage cp.async pipeline over 8 K-chunks of 16.
// ---------------------------------------------------------------------------
__global__ __launch_bounds__(256, 2) void g_kernel(const float* __restrict__ W_hh,
                                                   int mp) {
    __shared__ float As[3][64][20];
    __shared__ float Bs[3][64][20];
    const int N = mp * MSZ;
    const float* A = g_traj + (size_t)c_TOFF[mp] * (NB * MSZ);
    float* C = g_G + c_GOFF[mp];
    const int row0 = blockIdx.x * 64;
    const int n0 = blockIdx.y * 64;
    const int tid = threadIdx.x;
    const int tx = tid & 15;
    const int ty = tid >> 4;

    const int lrow = tid >> 2, lc4 = tid & 3;
    const int STG = 64 * 20 * 4;    // stage stride in bytes

    const float* ApG = A + (size_t)(row0 + lrow) * MSZ + lc4 * 4;
    const float* BpG = W_hh + (size_t)(n0 + lrow) * NH + mp * MSZ + lc4 * 4;
    const unsigned int sA =
        (unsigned int)__cvta_generic_to_shared(&As[0][lrow][lc4 * 4]);
    const unsigned int sB =
        (unsigned int)__cvta_generic_to_shared(&Bs[0][lrow][lc4 * 4]);

    // prologue: stages 0 and 1 in flight
    cp16(sA, ApG); cp16(sB, BpG); cp_commit();
    cp16(sA + STG, ApG + 16); cp16(sB + STG, BpG + 16); cp_commit();

    unsigned long long acc[4][4];
#pragma unroll
    for (int i = 0; i < 4; i++)
#pragma unroll
        for (int j = 0; j < 4; j++) acc[i][j] = 0ull;

#pragma unroll
    for (int c = 0; c < 8; c++) {
        if (c < 7) cp_wait1(); else cp_wait0();
        __syncthreads();
        if (c + 2 < 8) {
            const int st = (c + 2) % 3;
            cp16(sA + st * STG, ApG + (c + 2) * 16);
            cp16(sB + st * STG, BpG + (c + 2) * 16);
            cp_commit();
        }
        const int buf = c % 3;
#pragma unroll
        for (int k4 = 0; k4 < 4; k4++) {
            U4 af[4], bf[4];
#pragma unroll
            for (int i = 0; i < 4; i++)
                af[i].f = *(const float4*)&As[buf][ty * 4 + i][k4 * 4];
#pragma unroll
            for (int j = 0; j < 4; j++)
                bf[j].f = *(const float4*)&Bs[buf][tx + j * 16][k4 * 4];
#pragma unroll
            for (int i = 0; i < 4; i++)
#pragma unroll
                for (int j = 0; j < 4; j++) {
                    fma2(acc[i][j], af[i].u[0], bf[j].u[0]);
                    fma2(acc[i][j], af[i].u[1], bf[j].u[1]);
                }
        }
    }

#pragma unroll
    for (int i = 0; i < 4; i++)
#pragma unroll
        for (int j = 0; j < 4; j++) {
            U2 a;
            a.u = acc[i][j];
            C[(size_t)(row0 + ty * 4 + i) * N + n0 + tx + j * 16] =
                a.f.x + a.f.y;
        }
}

// ---------------------------------------------------------------------------
// fc partials: one CTA per stored state; 8 warps sweep the 128 batch rows.
// ---------------------------------------------------------------------------
__global__ __launch_bounds__(256) void pout_kernel(
    const float* __restrict__ fc_w) {
    const int gs = blockIdx.x;
    const int warp = threadIdx.x >> 5;
    const int lane = threadIdx.x & 31;
    int m = 0;
#pragma unroll
    for (int j = 1; j < 8; j++)
        if (gs >= c_TOFF[j]) m = j;
    const int col = m * MSZ + lane * 4;
    const float4 w0 = *(const float4*)(fc_w + col);
    const float4 w1 = *(const float4*)(fc_w + NH + col);
    const float* base = g_traj + (size_t)gs * (NB * MSZ);

    for (int b = warp; b < NB; b += 8) {
        const float4 v = *(const float4*)(base + (size_t)b * MSZ + lane * 4);
        float a0 = v.x * w0.x + v.y * w0.y + v.z * w0.z + v.w * w0.w;
        float a1 = v.x * w1.x + v.y * w1.y + v.z * w1.z + v.w * w1.w;
#pragma unroll
        for (int off = 16; off > 0; off >>= 1) {
            a0 += __shfl_xor_sync(0xffffffffu, a0, off);
            a1 += __shfl_xor_sync(0xffffffffu, a1, off);
        }
        if (lane == 0) {
            g_pout[((size_t)gs * NB + b) * 2 + 0] = a0;
            g_pout[((size_t)gs * NB + b) * 2 + 1] = a1;
        }
    }
}

// ---------------------------------------------------------------------------
// out[b,t,i] = fc_b[i] + sum_m pout[state_of(m,t), b, i]
// ---------------------------------------------------------------------------
__global__ void assemble_kernel(const float* __restrict__ fc_b,
                                float* __restrict__ out) {
    const int idx = blockIdx.x * blockDim.x + threadIdx.x;  // b*512 + t
    const int b = idx >> 9;
    const int t = idx & 511;
    float o0 = fc_b[0];
    float o1 = fc_b[1];
#pragma unroll
    for (int m = 0; m < NMOD; m++) {
        const int gs = c_TOFF[m] + (t >> m) + 1;
        o0 += g_pout[((size_t)gs * NB + b) * 2 + 0];
        o1 += g_pout[((size_t)gs * NB + b) * 2 + 1];
    }
    out[(size_t)idx * 2 + 0] = o0;
    out[(size_t)idx * 2 + 1] = o1;
}

// ---------------------------------------------------------------------------
extern "C" void kernel_launch(void* const* d_in, const int* in_sizes, int n_in,
                              void* d_out, int out_size) {
    const float* x     = (const float*)d_in[0];
    const float* W_ih  = (const float*)d_in[1];
    const float* W_hh  = (const float*)d_in[2];
    const float* fc_w  = (const float*)d_in[3];
    const float* fc_b  = (const float*)d_in[4];
    const float* enc_w = (const float*)d_in[5];
    float* out = (float*)d_out;

    // S_mp = {_,257,129,65,33,17,9,5}; grid = (2*S_mp, 2*mp) for 64x64 tiles
    chain_kernel<7><<<NB, MSZ>>>(x, W_ih, W_hh, enc_w);
    g_kernel<<<dim3(10, 14), 256>>>(W_hh, 7);
    chain_kernel<6><<<NB, MSZ>>>(x, W_ih, W_hh, enc_w);
    g_kernel<<<dim3(18, 12), 256>>>(W_hh, 6);
    chain_kernel<5><<<NB, MSZ>>>(x, W_ih, W_hh, enc_w);
    g_kernel<<<dim3(34, 10), 256>>>(W_hh, 5);
    chain_kernel<4><<<NB, MSZ>>>(x, W_ih, W_hh, enc_w);
    g_kernel<<<dim3(66, 8), 256>>>(W_hh, 4);
    chain_kernel<3><<<NB, MSZ>>>(x, W_ih, W_hh, enc_w);
    g_kernel<<<dim3(130, 6), 256>>>(W_hh, 3);
    chain_kernel<2><<<NB, MSZ>>>(x, W_ih, W_hh, enc_w);
    g_kernel<<<dim3(258, 4), 256>>>(W_hh, 2);
    chain_kernel<1><<<NB, MSZ>>>(x, W_ih, W_hh, enc_w);
    g_kernel<<<dim3(514, 2), 256>>>(W_hh, 1);
    chain_kernel<0><<<NB, MSZ>>>(x, W_ih, W_hh, enc_w);

    pout_kernel<<<1028, 256>>>(fc_w);
    assemble_kernel<<<(NB * NT) / 256, 256>>>(fc_b, out);
}

// round 9
// speedup vs baseline: 1.2659x; 1.0280x over previous
#include <cuda_runtime.h>
#include <math.h>

// Clockwork RNN, hierarchically decomposed.
// B=128, T=512, I=2, H=1024, NM=8, MS=128.
// Round 9: g_kernel -> 128 thr/CTA, 64x64 tile, 8x4 per-thread micro-tile,
// 4 CTAs/SM (independent barrier domains), cp.async 3-stage pipeline.
// Chains/pout/assemble identical to R8.

#define NB   128
#define NT   512
#define NH   1024
#define NMOD 8
#define MSZ  128

__constant__ int c_TOFF[8] = {0, 513, 770, 899, 964, 997, 1014, 1023};
__constant__ long long c_GOFF[8] = {0, 0, 4210688, 8437760, 11632640,
                                    13795328, 15187968, 16072704};

__device__ float g_traj[16842752];   // 1028 states * 128 b * 128
__device__ float g_G[16646144];      // per-module context GEMM outputs
__device__ float g_pout[1028 * NB * 2];

// packed f32x2 helpers ------------------------------------------------------
__device__ __forceinline__ void fma2(unsigned long long& d,
                                     unsigned long long a,
                                     unsigned long long b) {
    asm("fma.rn.f32x2 %0, %1, %2, %0;" : "+l"(d) : "l"(a), "l"(b));
}
__device__ __forceinline__ unsigned long long add2(unsigned long long a,
                                                   unsigned long long b) {
    unsigned long long d;
    asm("add.rn.f32x2 %0, %1, %2;" : "=l"(d) : "l"(a), "l"(b));
    return d;
}
union U4 { float4 f; unsigned long long u[2]; };
union U2 { unsigned long long u; float2 f; };

__device__ __forceinline__ float fast_tanh(float v) {
    float e = __expf(2.f * v);
    return 1.f - __fdividef(2.f, e + 1.f);
}

__device__ __forceinline__ void cp16(unsigned int dst, const void* src) {
    asm volatile("cp.async.ca.shared.global [%0], [%1], 16;"
                 :: "r"(dst), "l"(src));
}
__device__ __forceinline__ void cp_commit() {
    asm volatile("cp.async.commit_group;");
}
__device__ __forceinline__ void cp_wait1() {
    asm volatile("cp.async.wait_group 1;" ::: "memory");
}
__device__ __forceinline__ void cp_wait0() {
    asm volatile("cp.async.wait_group 0;" ::: "memory");
}

// ---------------------------------------------------------------------------
// Sequential diagonal chain for module M (128 thr, 1 barrier/step).
// Weight block staged through smem with coalesced loads (2 passes). (R8)
// ---------------------------------------------------------------------------
template <int M>
__global__ __launch_bounds__(MSZ, 1) void chain_kernel(
    const float* __restrict__ x,
    const float* __restrict__ W_ih,
    const float* __restrict__ W_hh,
    const float* __restrict__ enc_w) {
    const int b = blockIdx.x;
    const int r = threadIdx.x;
    const int mbase = M * MSZ;
    __shared__ float h_s[2][MSZ];
    __shared__ float Wst[64][132];

    unsigned long long Wp[MSZ / 2];
#pragma unroll
    for (int pass = 0; pass < 2; pass++) {
#pragma unroll
        for (int i = 0; i < 16; i++) {
            const int idx = i * 128 + r;
            const int row = idx >> 5;
            const int c4 = idx & 31;
            *(float4*)&Wst[row][c4 * 4] =
                *(const float4*)(W_hh +
                                 (size_t)(mbase + pass * 64 + row) * NH +
                                 mbase + c4 * 4);
        }
        __syncthreads();
        if ((r >> 6) == pass) {
            const int rr = r & 63;
#pragma unroll
            for (int c4 = 0; c4 < 32; c4++) {
                U4 w;
                w.f = *(const float4*)&Wst[rr][c4 * 4];
                Wp[2 * c4 + 0] = w.u[0];
                Wp[2 * c4 + 1] = w.u[1];
            }
        }
        __syncthreads();
    }

    const float wih0 = W_ih[(mbase + r) * 2 + 0];
    const float wih1 = W_ih[(mbase + r) * 2 + 1];

    const float x00 = x[(size_t)b * (NT + 1) * 2 + 0];
    const float x01 = x[(size_t)b * (NT + 1) * 2 + 1];
    const float h0v = x00 * enc_w[(mbase + r) * 2 + 0] +
                      x01 * enc_w[(mbase + r) * 2 + 1];
    const size_t tbase = ((size_t)c_TOFF[M] * NB + b) * MSZ;
    h_s[0][r] = h0v;
    g_traj[tbase + r] = h0v;
    __syncthreads();

    const int K = NT >> M;

    float xn0 = x[((size_t)b * (NT + 1) + 1) * 2 + 0];
    float xn1 = x[((size_t)b * (NT + 1) + 1) * 2 + 1];
    float gg[8];
#pragma unroll
    for (int mp = M + 1; mp < NMOD; mp++)
        gg[mp - M - 1] =
            g_G[c_GOFF[mp] + (size_t)b * (mp * MSZ) + mbase + r];

    int p = 0;
    for (int k = 0; k < K; k++) {
        float gsum = xn0 * wih0 + xn1 * wih1;
#pragma unroll
        for (int mp = M + 1; mp < NMOD; mp++) gsum += gg[mp - M - 1];

        float xt0 = 0.f, xt1 = 0.f, gt[8];
        if (k + 1 < K) {
            const int t2 = (k + 1) << M;
            xt0 = x[((size_t)b * (NT + 1) + (t2 + 1)) * 2 + 0];
            xt1 = x[((size_t)b * (NT + 1) + (t2 + 1)) * 2 + 1];
#pragma unroll
            for (int mp = M + 1; mp < NMOD; mp++) {
                const int s = ((t2 - 1) >> mp) + 1;
                gt[mp - M - 1] = g_G[c_GOFF[mp] +
                                     (size_t)(s * NB + b) * (mp * MSZ) +
                                     mbase + r];
            }
        }

        unsigned long long acc[8] = {0, 0, 0, 0, 0, 0, 0, 0};
        const float4* h4 = (const float4*)h_s[p];
#pragma unroll
        for (int c4 = 0; c4 < MSZ / 4; c4++) {
            U4 hv;
            hv.f = h4[c4];
            fma2(acc[(2 * c4) & 7], Wp[2 * c4], hv.u[0]);
            fma2(acc[(2 * c4 + 1) & 7], Wp[2 * c4 + 1], hv.u[1]);
        }
        acc[0] = add2(acc[0], acc[1]);
        acc[2] = add2(acc[2], acc[3]);
        acc[4] = add2(acc[4], acc[5]);
        acc[6] = add2(acc[6], acc[7]);
        acc[0] = add2(acc[0], acc[2]);
        acc[4] = add2(acc[4], acc[6]);
        acc[0] = add2(acc[0], acc[4]);
        U2 a;
        a.u = acc[0];
        const float hn = fast_tanh(a.f.x + a.f.y + gsum);

        h_s[p ^ 1][r] = hn;
        g_traj[tbase + (size_t)(k + 1) * (NB * MSZ) + r] = hn;
        __syncthreads();
        p ^= 1;

        xn0 = xt0; xn1 = xt1;
#pragma unroll
        for (int mp = M + 1; mp < NMOD; mp++) gg[mp - M - 1] = gt[mp - M - 1];
    }
}

// ---------------------------------------------------------------------------
// G_{mp} = Traj_{mp} (S_mp*128 x 128) @ W_hh[0:mp*128, mp-block]^T
// 64x64 tile, 128 threads, 8x4 packed-f32x2 micro-tile, 4 CTAs/SM.
// 3-stage cp.async pipeline over 8 K-chunks of 16.
// ---------------------------------------------------------------------------
__global__ __launch_bounds__(128, 4) void g_kernel(const float* __restrict__ W_hh,
                                                   int mp) {
    __shared__ float As[3][64][20];
    __shared__ float Bs[3][64][20];
    const int N = mp * MSZ;
    const float* A = g_traj + (size_t)c_TOFF[mp] * (NB * MSZ);
    float* C = g_G + c_GOFF[mp];
    const int row0 = blockIdx.x * 64;
    const int n0 = blockIdx.y * 64;
    const int tid = threadIdx.x;
    const int tx = tid & 15;   // 16 col lanes: cols {tx, tx+16, tx+32, tx+48}
    const int ty = tid >> 4;   // 8 row groups of 8

    // loader role: 2 float4 per array per thread
    const int lr0 = tid >> 2, lc4 = tid & 3;      // slots tid and tid+128
    const int lr1 = (tid + 128) >> 2;
    const int STG = 64 * 20 * 4;                  // stage stride in bytes

    const float* ApG0 = A + (size_t)(row0 + lr0) * MSZ + lc4 * 4;
    const float* ApG1 = A + (size_t)(row0 + lr1) * MSZ + lc4 * 4;
    const float* BpG0 = W_hh + (size_t)(n0 + lr0) * NH + mp * MSZ + lc4 * 4;
    const float* BpG1 = W_hh + (size_t)(n0 + lr1) * NH + mp * MSZ + lc4 * 4;
    const unsigned int sA0 =
        (unsigned int)__cvta_generic_to_shared(&As[0][lr0][lc4 * 4]);
    const unsigned int sA1 =
        (unsigned int)__cvta_generic_to_shared(&As[0][lr1][lc4 * 4]);
    const unsigned int sB0 =
        (unsigned int)__cvta_generic_to_shared(&Bs[0][lr0][lc4 * 4]);
    const unsigned int sB1 =
        (unsigned int)__cvta_generic_to_shared(&Bs[0][lr1][lc4 * 4]);

    // prologue: stages 0 and 1 in flight
    cp16(sA0, ApG0); cp16(sA1, ApG1);
    cp16(sB0, BpG0); cp16(sB1, BpG1); cp_commit();
    cp16(sA0 + STG, ApG0 + 16); cp16(sA1 + STG, ApG1 + 16);
    cp16(sB0 + STG, BpG0 + 16); cp16(sB1 + STG, BpG1 + 16); cp_commit();

    unsigned long long acc[8][4];
#pragma unroll
    for (int i = 0; i < 8; i++)
#pragma unroll
        for (int j = 0; j < 4; j++) acc[i][j] = 0ull;

#pragma unroll
    for (int c = 0; c < 8; c++) {
        if (c < 7) cp_wait1(); else cp_wait0();
        __syncthreads();
        if (c + 2 < 8) {
            const int st = (c + 2) % 3;
            cp16(sA0 + st * STG, ApG0 + (c + 2) * 16);
            cp16(sA1 + st * STG, ApG1 + (c + 2) * 16);
            cp16(sB0 + st * STG, BpG0 + (c + 2) * 16);
            cp16(sB1 + st * STG, BpG1 + (c + 2) * 16);
            cp_commit();
        }
        const int buf = c % 3;
#pragma unroll
        for (int k4 = 0; k4 < 4; k4++) {
            U4 bf[4];
#pragma unroll
            for (int j = 0; j < 4; j++)
                bf[j].f = *(const float4*)&Bs[buf][tx + j * 16][k4 * 4];
#pragma unroll
            for (int half = 0; half < 2; half++) {
                U4 af[4];
#pragma unroll
                for (int i2 = 0; i2 < 4; i2++)
                    af[i2].f = *(const float4*)
                        &As[buf][ty * 8 + half * 4 + i2][k4 * 4];
#pragma unroll
                for (int i2 = 0; i2 < 4; i2++)
#pragma unroll
                    for (int j = 0; j < 4; j++) {
                        fma2(acc[half * 4 + i2][j], af[i2].u[0], bf[j].u[0]);
                        fma2(acc[half * 4 + i2][j], af[i2].u[1], bf[j].u[1]);
                    }
            }
        }
    }

#pragma unroll
    for (int i = 0; i < 8; i++)
#pragma unroll
        for (int j = 0; j < 4; j++) {
            U2 a;
            a.u = acc[i][j];
            C[(size_t)(row0 + ty * 8 + i) * N + n0 + tx + j * 16] =
                a.f.x + a.f.y;
        }
}

// ---------------------------------------------------------------------------
// fc partials: one CTA per stored state; 8 warps sweep the 128 batch rows.
// ---------------------------------------------------------------------------
__global__ __launch_bounds__(256) void pout_kernel(
    const float* __restrict__ fc_w) {
    const int gs = blockIdx.x;
    const int warp = threadIdx.x >> 5;
    const int lane = threadIdx.x & 31;
    int m = 0;
#pragma unroll
    for (int j = 1; j < 8; j++)
        if (gs >= c_TOFF[j]) m = j;
    const int col = m * MSZ + lane * 4;
    const float4 w0 = *(const float4*)(fc_w + col);
    const float4 w1 = *(const float4*)(fc_w + NH + col);
    const float* base = g_traj + (size_t)gs * (NB * MSZ);

    for (int b = warp; b < NB; b += 8) {
        const float4 v = *(const float4*)(base + (size_t)b * MSZ + lane * 4);
        float a0 = v.x * w0.x + v.y * w0.y + v.z * w0.z + v.w * w0.w;
        float a1 = v.x * w1.x + v.y * w1.y + v.z * w1.z + v.w * w1.w;
#pragma unroll
        for (int off = 16; off > 0; off >>= 1) {
            a0 += __shfl_xor_sync(0xffffffffu, a0, off);
            a1 += __shfl_xor_sync(0xffffffffu, a1, off);
        }
        if (lane == 0) {
            g_pout[((size_t)gs * NB + b) * 2 + 0] = a0;
            g_pout[((size_t)gs * NB + b) * 2 + 1] = a1;
        }
    }
}

// ---------------------------------------------------------------------------
// out[b,t,i] = fc_b[i] + sum_m pout[state_of(m,t), b, i]
// ---------------------------------------------------------------------------
__global__ void assemble_kernel(const float* __restrict__ fc_b,
                                float* __restrict__ out) {
    const int idx = blockIdx.x * blockDim.x + threadIdx.x;  // b*512 + t
    const int b = idx >> 9;
    const int t = idx & 511;
    float o0 = fc_b[0];
    float o1 = fc_b[1];
#pragma unroll
    for (int m = 0; m < NMOD; m++) {
        const int gs = c_TOFF[m] + (t >> m) + 1;
        o0 += g_pout[((size_t)gs * NB + b) * 2 + 0];
        o1 += g_pout[((size_t)gs * NB + b) * 2 + 1];
    }
    out[(size_t)idx * 2 + 0] = o0;
    out[(size_t)idx * 2 + 1] = o1;
}

// ---------------------------------------------------------------------------
extern "C" void kernel_launch(void* const* d_in, const int* in_sizes, int n_in,
                              void* d_out, int out_size) {
    const float* x     = (const float*)d_in[0];
    const float* W_ih  = (const float*)d_in[1];
    const float* W_hh  = (const float*)d_in[2];
    const float* fc_w  = (const float*)d_in[3];
    const float* fc_b  = (const float*)d_in[4];
    const float* enc_w = (const float*)d_in[5];
    float* out = (float*)d_out;

    // S_mp = {_,257,129,65,33,17,9,5}; grid = (2*S_mp, 2*mp) for 64x64 tiles
    chain_kernel<7><<<NB, MSZ>>>(x, W_ih, W_hh, enc_w);
    g_kernel<<<dim3(10, 14), 128>>>(W_hh, 7);
    chain_kernel<6><<<NB, MSZ>>>(x, W_ih, W_hh, enc_w);
    g_kernel<<<dim3(18, 12), 128>>>(W_hh, 6);
    chain_kernel<5><<<NB, MSZ>>>(x, W_ih, W_hh, enc_w);
    g_kernel<<<dim3(34, 10), 128>>>(W_hh, 5);
    chain_kernel<4><<<NB, MSZ>>>(x, W_ih, W_hh, enc_w);
    g_kernel<<<dim3(66, 8), 128>>>(W_hh, 4);
    chain_kernel<3><<<NB, MSZ>>>(x, W_ih, W_hh, enc_w);
    g_kernel<<<dim3(130, 6), 128>>>(W_hh, 3);
    chain_kernel<2><<<NB, MSZ>>>(x, W_ih, W_hh, enc_w);
    g_kernel<<<dim3(258, 4), 128>>>(W_hh, 2);
    chain_kernel<1><<<NB, MSZ>>>(x, W_ih, W_hh, enc_w);
    g_kernel<<<dim3(514, 2), 128>>>(W_hh, 1);
    chain_kernel<0><<<NB, MSZ>>>(x, W_ih, W_hh, enc_w);

    pout_kernel<<<1028, 256>>>(fc_w);
    assemble_kernel<<<(NB * NT) / 256, 256>>>(fc_b, out);
}

// round 10
// speedup vs baseline: 1.3484x; 1.0652x over previous
#include <cuda_runtime.h>
#include <math.h>

// Clockwork RNN, hierarchically decomposed.
// B=128, T=512, I=2, H=1024, NM=8, MS=128.
// Round 10: chains cache g_G gathers behind per-mp pointers with predicated
// reloads (values change only when source state index increments); GEMMs for
// mp>=4 use 32-row tiles (2x CTAs) to cut wave latency on starved grids.

#define NB   128
#define NT   512
#define NH   1024
#define NMOD 8
#define MSZ  128

__constant__ int c_TOFF[8] = {0, 513, 770, 899, 964, 997, 1014, 1023};
__constant__ long long c_GOFF[8] = {0, 0, 4210688, 8437760, 11632640,
                                    13795328, 15187968, 16072704};

__device__ float g_traj[16842752];   // 1028 states * 128 b * 128
__device__ float g_G[16646144];      // per-module context GEMM outputs
__device__ float g_pout[1028 * NB * 2];

// packed f32x2 helpers ------------------------------------------------------
__device__ __forceinline__ void fma2(unsigned long long& d,
                                     unsigned long long a,
                                     unsigned long long b) {
    asm("fma.rn.f32x2 %0, %1, %2, %0;" : "+l"(d) : "l"(a), "l"(b));
}
__device__ __forceinline__ unsigned long long add2(unsigned long long a,
                                                   unsigned long long b) {
    unsigned long long d;
    asm("add.rn.f32x2 %0, %1, %2;" : "=l"(d) : "l"(a), "l"(b));
    return d;
}
union U4 { float4 f; unsigned long long u[2]; };
union U2 { unsigned long long u; float2 f; };

__device__ __forceinline__ float fast_tanh(float v) {
    float e = __expf(2.f * v);
    return 1.f - __fdividef(2.f, e + 1.f);
}

__device__ __forceinline__ void cp16(unsigned int dst, const void* src) {
    asm volatile("cp.async.ca.shared.global [%0], [%1], 16;"
                 :: "r"(dst), "l"(src));
}
__device__ __forceinline__ void cp_commit() {
    asm volatile("cp.async.commit_group;");
}
__device__ __forceinline__ void cp_wait1() {
    asm volatile("cp.async.wait_group 1;" ::: "memory");
}
__device__ __forceinline__ void cp_wait0() {
    asm volatile("cp.async.wait_group 0;" ::: "memory");
}

// ---------------------------------------------------------------------------
// Sequential diagonal chain for module M (128 thr, 1 barrier/step).
// Gathers: per-mp pointer bumped by compile-time stride when the source
// state changes (trigger: (t2-1) mod 2^mp < 2^M); predicated LDG otherwise
// register reuse. Pointer = base + s*NB*mp*MSZ == old explicit index.
// ---------------------------------------------------------------------------
template <int M>
__global__ __launch_bounds__(MSZ, 1) void chain_kernel(
    const float* __restrict__ x,
    const float* __restrict__ W_ih,
    const float* __restrict__ W_hh,
    const float* __restrict__ enc_w) {
    const int b = blockIdx.x;
    const int r = threadIdx.x;
    const int mbase = M * MSZ;
    __shared__ float h_s[2][MSZ];
    __shared__ float Wst[64][132];

    unsigned long long Wp[MSZ / 2];
#pragma unroll
    for (int pass = 0; pass < 2; pass++) {
#pragma unroll
        for (int i = 0; i < 16; i++) {
            const int idx = i * 128 + r;
            const int row = idx >> 5;
            const int c4 = idx & 31;
            *(float4*)&Wst[row][c4 * 4] =
                *(const float4*)(W_hh +
                                 (size_t)(mbase + pass * 64 + row) * NH +
                                 mbase + c4 * 4);
        }
        __syncthreads();
        if ((r >> 6) == pass) {
            const int rr = r & 63;
#pragma unroll
            for (int c4 = 0; c4 < 32; c4++) {
                U4 w;
                w.f = *(const float4*)&Wst[rr][c4 * 4];
                Wp[2 * c4 + 0] = w.u[0];
                Wp[2 * c4 + 1] = w.u[1];
            }
        }
        __syncthreads();
    }

    const float wih0 = W_ih[(mbase + r) * 2 + 0];
    const float wih1 = W_ih[(mbase + r) * 2 + 1];

    const float x00 = x[(size_t)b * (NT + 1) * 2 + 0];
    const float x01 = x[(size_t)b * (NT + 1) * 2 + 1];
    const float h0v = x00 * enc_w[(mbase + r) * 2 + 0] +
                      x01 * enc_w[(mbase + r) * 2 + 1];
    const size_t tbase = ((size_t)c_TOFF[M] * NB + b) * MSZ;
    h_s[0][r] = h0v;
    g_traj[tbase + r] = h0v;
    __syncthreads();

    const int K = NT >> M;
    constexpr int NG = (NMOD - 1 - M) > 0 ? (NMOD - 1 - M) : 1;

    // gather pointers at s=0 and current values
    const float* gp[NG];
    float gg[NG];
#pragma unroll
    for (int mp = M + 1; mp < NMOD; mp++) {
        gp[mp - M - 1] = g_G + c_GOFF[mp] + (size_t)b * (mp * MSZ) +
                         mbase + r;
        gg[mp - M - 1] = *gp[mp - M - 1];
    }

    float xn0 = x[((size_t)b * (NT + 1) + 1) * 2 + 0];
    float xn1 = x[((size_t)b * (NT + 1) + 1) * 2 + 1];

    int p = 0;
    for (int k = 0; k < K; k++) {
        float gsum = xn0 * wih0 + xn1 * wih1;
#pragma unroll
        for (int mp = M + 1; mp < NMOD; mp++) gsum += gg[mp - M - 1];

        // prefetch next step's externals
        const int t2 = (k + 1) << M;
        float xt0 = 0.f, xt1 = 0.f;
        if (k + 1 < K) {
            xt0 = x[((size_t)b * (NT + 1) + (t2 + 1)) * 2 + 0];
            xt1 = x[((size_t)b * (NT + 1) + (t2 + 1)) * 2 + 1];
        }
        float gt[NG];
#pragma unroll
        for (int mp = M + 1; mp < NMOD; mp++) {
            const int i = mp - M - 1;
            // source state s increments iff (t2-1) mod 2^mp < 2^M
            const bool trig = (((t2 - 1) & ((1 << mp) - 1)) < (1 << M));
            if (trig) {
                gp[i] += (size_t)NB * mp * MSZ;
                gt[i] = __ldg(gp[i]);
            } else {
                gt[i] = gg[i];
            }
        }

        unsigned long long acc[8] = {0, 0, 0, 0, 0, 0, 0, 0};
        const float4* h4 = (const float4*)h_s[p];
#pragma unroll
        for (int c4 = 0; c4 < MSZ / 4; c4++) {
            U4 hv;
            hv.f = h4[c4];
            fma2(acc[(2 * c4) & 7], Wp[2 * c4], hv.u[0]);
            fma2(acc[(2 * c4 + 1) & 7], Wp[2 * c4 + 1], hv.u[1]);
        }
        acc[0] = add2(acc[0], acc[1]);
        acc[2] = add2(acc[2], acc[3]);
        acc[4] = add2(acc[4], acc[5]);
        acc[6] = add2(acc[6], acc[7]);
        acc[0] = add2(acc[0], acc[2]);
        acc[4] = add2(acc[4], acc[6]);
        acc[0] = add2(acc[0], acc[4]);
        U2 a;
        a.u = acc[0];
        const float hn = fast_tanh(a.f.x + a.f.y + gsum);

        h_s[p ^ 1][r] = hn;
        g_traj[tbase + (size_t)(k + 1) * (NB * MSZ) + r] = hn;
        __syncthreads();
        p ^= 1;

        xn0 = xt0; xn1 = xt1;
#pragma unroll
        for (int mp = M + 1; mp < NMOD; mp++) gg[mp - M - 1] = gt[mp - M - 1];
    }
}

// ---------------------------------------------------------------------------
// G_{mp} = Traj_{mp} (S_mp*128 x RT-tiles) @ W_hh[0:mp*128, mp-block]^T
// RT x 64 tile (RT=64 or 32), 128 threads, (RT/8)x4 packed micro-tile.
// 3-stage cp.async pipeline over 8 K-chunks of 16.
// RT=32 for small grids (mp>=4): 2x CTAs, half per-CTA latency.
// ---------------------------------------------------------------------------
template <int RT>
__global__ __launch_bounds__(128, 4) void g_kernel(const float* __restrict__ W_hh,
                                                   int mp) {
    constexpr int RPT = RT / 8;          // rows per thread
    __shared__ float As[3][RT][20];
    __shared__ float Bs[3][64][20];
    const int N = mp * MSZ;
    const float* A = g_traj + (size_t)c_TOFF[mp] * (NB * MSZ);
    float* C = g_G + c_GOFF[mp];
    const int row0 = blockIdx.x * RT;
    const int n0 = blockIdx.y * 64;
    const int tid = threadIdx.x;
    const int tx = tid & 15;   // cols {tx, tx+16, tx+32, tx+48}
    const int ty = tid >> 4;   // 8 row groups of RPT

    const int lr0 = tid >> 2, lc4 = tid & 3;
    const int lr1 = (tid + 128) >> 2;            // only used when RT==64
    const int STGA = RT * 20 * 4;
    const int STGB = 64 * 20 * 4;

    const float* ApG0 = A + (size_t)(row0 + lr0) * MSZ + lc4 * 4;
    const float* ApG1 = A + (size_t)(row0 + lr1) * MSZ + lc4 * 4;
    const float* BpG0 = W_hh + (size_t)(n0 + lr0) * NH + mp * MSZ + lc4 * 4;
    const float* BpG1 = W_hh + (size_t)(n0 + lr1) * NH + mp * MSZ + lc4 * 4;
    const unsigned int sA0 =
        (unsigned int)__cvta_generic_to_shared(&As[0][lr0][lc4 * 4]);
    const unsigned int sB0 =
        (unsigned int)__cvta_generic_to_shared(&Bs[0][lr0][lc4 * 4]);
    const unsigned int sB1 =
        (unsigned int)__cvta_generic_to_shared(&Bs[0][lr1][lc4 * 4]);
    unsigned int sA1 = 0;
    if (RT == 64)
        sA1 = (unsigned int)__cvta_generic_to_shared(&As[0][(tid + 128) >> 2][lc4 * 4]);

    // prologue: stages 0 and 1 in flight
    cp16(sA0, ApG0);
    if (RT == 64) cp16(sA1, ApG1);
    cp16(sB0, BpG0); cp16(sB1, BpG1); cp_commit();
    cp16(sA0 + STGA, ApG0 + 16);
    if (RT == 64) cp16(sA1 + STGA, ApG1 + 16);
    cp16(sB0 + STGB, BpG0 + 16); cp16(sB1 + STGB, BpG1 + 16); cp_commit();

    unsigned long long acc[RPT][4];
#pragma unroll
    for (int i = 0; i < RPT; i++)
#pragma unroll
        for (int j = 0; j < 4; j++) acc[i][j] = 0ull;

#pragma unroll
    for (int c = 0; c < 8; c++) {
        if (c < 7) cp_wait1(); else cp_wait0();
        __syncthreads();
        if (c + 2 < 8) {
            const int st = (c + 2) % 3;
            cp16(sA0 + st * STGA, ApG0 + (c + 2) * 16);
            if (RT == 64) cp16(sA1 + st * STGA, ApG1 + (c + 2) * 16);
            cp16(sB0 + st * STGB, BpG0 + (c + 2) * 16);
            cp16(sB1 + st * STGB, BpG1 + (c + 2) * 16);
            cp_commit();
        }
        const int buf = c % 3;
#pragma unroll
        for (int k4 = 0; k4 < 4; k4++) {
            U4 bf[4];
#pragma unroll
            for (int j = 0; j < 4; j++)
                bf[j].f = *(const float4*)&Bs[buf][tx + j * 16][k4 * 4];
#pragma unroll
            for (int g = 0; g < RPT / 4; g++) {
                U4 af[4];
#pragma unroll
                for (int i2 = 0; i2 < 4; i2++)
                    af[i2].f = *(const float4*)
                        &As[buf][ty * RPT + g * 4 + i2][k4 * 4];
#pragma unroll
                for (int i2 = 0; i2 < 4; i2++)
#pragma unroll
                    for (int j = 0; j < 4; j++) {
                        fma2(acc[g * 4 + i2][j], af[i2].u[0], bf[j].u[0]);
                        fma2(acc[g * 4 + i2][j], af[i2].u[1], bf[j].u[1]);
                    }
            }
        }
    }

#pragma unroll
    for (int i = 0; i < RPT; i++)
#pragma unroll
        for (int j = 0; j < 4; j++) {
            U2 a;
            a.u = acc[i][j];
            C[(size_t)(row0 + ty * RPT + i) * N + n0 + tx + j * 16] =
                a.f.x + a.f.y;
        }
}

// ---------------------------------------------------------------------------
// fc partials: one CTA per stored state; 8 warps sweep the 128 batch rows.
// ---------------------------------------------------------------------------
__global__ __launch_bounds__(256) void pout_kernel(
    const float* __restrict__ fc_w) {
    const int gs = blockIdx.x;
    const int warp = threadIdx.x >> 5;
    const int lane = threadIdx.x & 31;
    int m = 0;
#pragma unroll
    for (int j = 1; j < 8; j++)
        if (gs >= c_TOFF[j]) m = j;
    const int col = m * MSZ + lane * 4;
    const float4 w0 = *(const float4*)(fc_w + col);
    const float4 w1 = *(const float4*)(fc_w + NH + col);
    const float* base = g_traj + (size_t)gs * (NB * MSZ);

    for (int b = warp; b < NB; b += 8) {
        const float4 v = *(const float4*)(base + (size_t)b * MSZ + lane * 4);
        float a0 = v.x * w0.x + v.y * w0.y + v.z * w0.z + v.w * w0.w;
        float a1 = v.x * w1.x + v.y * w1.y + v.z * w1.z + v.w * w1.w;
#pragma unroll
        for (int off = 16; off > 0; off >>= 1) {
            a0 += __shfl_xor_sync(0xffffffffu, a0, off);
            a1 += __shfl_xor_sync(0xffffffffu, a1, off);
        }
        if (lane == 0) {
            g_pout[((size_t)gs * NB + b) * 2 + 0] = a0;
            g_pout[((size_t)gs * NB + b) * 2 + 1] = a1;
        }
    }
}

// ---------------------------------------------------------------------------
// out[b,t,i] = fc_b[i] + sum_m pout[state_of(m,t), b, i]
// ---------------------------------------------------------------------------
__global__ void assemble_kernel(const float* __restrict__ fc_b,
                                float* __restrict__ out) {
    const int idx = blockIdx.x * blockDim.x + threadIdx.x;  // b*512 + t
    const int b = idx >> 9;
    const int t = idx & 511;
    float o0 = fc_b[0];
    float o1 = fc_b[1];
#pragma unroll
    for (int m = 0; m < NMOD; m++) {
        const int gs = c_TOFF[m] + (t >> m) + 1;
        o0 += g_pout[((size_t)gs * NB + b) * 2 + 0];
        o1 += g_pout[((size_t)gs * NB + b) * 2 + 1];
    }
    out[(size_t)idx * 2 + 0] = o0;
    out[(size_t)idx * 2 + 1] = o1;
}

// ---------------------------------------------------------------------------
extern "C" void kernel_launch(void* const* d_in, const int* in_sizes, int n_in,
                              void* d_out, int out_size) {
    const float* x     = (const float*)d_in[0];
    const float* W_ih  = (const float*)d_in[1];
    const float* W_hh  = (const float*)d_in[2];
    const float* fc_w  = (const float*)d_in[3];
    const float* fc_b  = (const float*)d_in[4];
    const float* enc_w = (const float*)d_in[5];
    float* out = (float*)d_out;

    // S_mp = {_,257,129,65,33,17,9,5}
    // mp>=4: 32-row tiles (grid rows = S*128/32 = 4S); mp<=3: 64-row (2S)
    chain_kernel<7><<<NB, MSZ>>>(x, W_ih, W_hh, enc_w);
    g_kernel<32><<<dim3(20, 14), 128>>>(W_hh, 7);
    chain_kernel<6><<<NB, MSZ>>>(x, W_ih, W_hh, enc_w);
    g_kernel<32><<<dim3(36, 12), 128>>>(W_hh, 6);
    chain_kernel<5><<<NB, MSZ>>>(x, W_ih, W_hh, enc_w);
    g_kernel<32><<<dim3(68, 10), 128>>>(W_hh, 5);
    chain_kernel<4><<<NB, MSZ>>>(x, W_ih, W_hh, enc_w);
    g_kernel<32><<<dim3(132, 8), 128>>>(W_hh, 4);
    chain_kernel<3><<<NB, MSZ>>>(x, W_ih, W_hh, enc_w);
    g_kernel<64><<<dim3(130, 6), 128>>>(W_hh, 3);
    chain_kernel<2><<<NB, MSZ>>>(x, W_ih, W_hh, enc_w);
    g_kernel<64><<<dim3(258, 4), 128>>>(W_hh, 2);
    chain_kernel<1><<<NB, MSZ>>>(x, W_ih, W_hh, enc_w);
    g_kernel<64><<<dim3(514, 2), 128>>>(W_hh, 1);
    chain_kernel<0><<<NB, MSZ>>>(x, W_ih, W_hh, enc_w);

    pout_kernel<<<1028, 256>>>(fc_w);
    assemble_kernel<<<(NB * NT) / 256, 256>>>(fc_b, out);
}